// round 11
// baseline (speedup 1.0000x reference)
#include <cuda_runtime.h>
#include <math.h>
#include <stdint.h>

#define NB    16
#define PTOT  1024
#define CD    256
#define HND   512
#define SEQL  20
#define MROWS (NB*PTOT)        /* 16384 */
#define KCONV 2304             /* 9 taps * 256 ch */

/* ---------------- scratch (device globals; no allocation allowed) -------- */
__device__ float g_featT [MROWS*CD];
__device__ float g_base  [MROWS*CD];
__device__ float g_t     [MROWS*CD];
__device__ float g_fea   [MROWS*CD];
__device__ float g_s1    [MROWS*CD];
__device__ float g_s2    [MROWS*CD];
__device__ float g_kv    [MROWS*2*CD];
__device__ float g_wConvT[KCONV*CD];
__device__ float g_wkvT  [CD*2*CD];
__device__ float g_woT   [CD*CD];
__device__ float g_w1T   [CD*CD];
__device__ float g_w2T   [CD*CD];
__device__ float g_hnTap [NB*CD*9];
__device__ float g_sconv [PTOT*CD];
__device__ float g_qhall [SEQL*NB*CD];
__device__ float g_qall  [SEQL*NB*CD];

/* ---------------- tf32 round helper (precompute only) -------------------- */
__device__ __forceinline__ float ftf32(float x)
{
    uint32_t u;
    asm("cvt.rna.tf32.f32 %0, %1;" : "=r"(u) : "f"(x));
    return __uint_as_float(u);
}

/* ---------------- cp.async helpers --------------------------------------- */
__device__ __forceinline__ void cp16(uint32_t d, const void* s, int sz)
{
    asm volatile("cp.async.cg.shared.global [%0], [%1], 16, %2;"
                 :: "r"(d), "l"(s), "r"(sz));
}
#define CP_COMMIT() asm volatile("cp.async.commit_group;")
#define CP_WAIT(n)  asm volatile("cp.async.wait_group %0;" :: "n"(n))

/* ---------------- generic 32x32 tiled transpose: dst[c][o] = src[o][c] --- */
__global__ void wtr_k(const float* __restrict__ src, float* __restrict__ dst,
                      int O, int Cc, long sStride, long dStride, int rnd)
{
    src += (size_t)blockIdx.z * sStride;
    dst += (size_t)blockIdx.z * dStride;
    __shared__ float tile[32][33];
    int o0 = blockIdx.x * 32, c0 = blockIdx.y * 32;
    int lx = threadIdx.x & 31, ly = threadIdx.x >> 5;
    #pragma unroll
    for (int i = ly; i < 32; i += 8)
        if (o0 + i < O && c0 + lx < Cc)
            tile[i][lx] = src[(size_t)(o0 + i) * Cc + c0 + lx];
    __syncthreads();
    #pragma unroll
    for (int i = ly; i < 32; i += 8)
        if (c0 + i < Cc && o0 + lx < O) {
            float v = tile[lx][i];
            dst[(size_t)(c0 + i) * O + o0 + lx] = rnd ? ftf32(v) : v;
        }
}

/* ---------------- conv weight relayout: [o][c][tap] -> [tap*256+c][o] ---- */
__global__ void wconv_k(const float* __restrict__ mw, float* __restrict__ dst)
{
    int k = blockIdx.x;
    int tap = k >> 8, c = k & 255;
    int o = threadIdx.x;
    dst[(size_t)k * CD + o] = ftf32(mw[((size_t)o * 776 + c) * 9 + tap]);
}

/* ---------------- hn tap sums -------------------------------------------- */
__global__ void hntap_k(const float* __restrict__ hn, const float* __restrict__ mw,
                        float* __restrict__ out)
{
    int n = blockIdx.x, o = threadIdx.x;
    __shared__ float h[HND];
    for (int i = o; i < HND; i += CD) h[i] = hn[(size_t)n * HND + i];
    __syncthreads();
    float acc[9];
    #pragma unroll
    for (int t = 0; t < 9; t++) acc[t] = 0.f;
    const float* wb = mw + ((size_t)o * 776 + 264) * 9;
    for (int c = 0; c < HND; c++) {
        float hv = h[c];
        #pragma unroll
        for (int t = 0; t < 9; t++) acc[t] += hv * wb[c * 9 + t];
    }
    #pragma unroll
    for (int t = 0; t < 9; t++) out[((size_t)n * CD + o) * 9 + t] = acc[t];
}

/* ---------------- spatial conv (invariant) ------------------------------- */
__global__ void sconv_k(const float* __restrict__ mw, float* __restrict__ out)
{
    int p = blockIdx.x, o = threadIdx.x;
    int h = p >> 5, w = p & 31;
    float acc = 0.f;
    const float* wb = mw + ((size_t)o * 776 + 256) * 9;
    for (int ky = 0; ky < 3; ky++) {
        int hh = h + ky - 1; if ((unsigned)hh >= 32u) continue;
        for (int kx = 0; kx < 3; kx++) {
            int ww = w + kx - 1; if ((unsigned)ww >= 32u) continue;
            float xmin = ww * (1.f/16.f) - 1.f, ymin = hh * (1.f/16.f) - 1.f;
            float xmax = (ww + 1) * (1.f/16.f) - 1.f, ymax = (hh + 1) * (1.f/16.f) - 1.f;
            float f[8] = {xmin, ymin, xmax, ymax,
                          0.5f*(xmin+xmax), 0.5f*(ymin+ymax), 1.f/32.f, 1.f/32.f};
            int t = ky * 3 + kx;
            #pragma unroll
            for (int c = 0; c < 8; c++) acc += f[c] * wb[c * 9 + t];
        }
    }
    out[(size_t)p * CD + o] = acc;
}

/* ---------------- base[n][p][o] = sconv + border-case hn taps ------------ */
__global__ void base_k(const float* __restrict__ sc, const float* __restrict__ ht,
                       float* __restrict__ base)
{
    int idx = blockIdx.x;
    int n = idx >> 10, p = idx & 1023;
    int o = threadIdx.x;
    int h = p >> 5, w = p & 31;
    int ky0 = (h == 0) ? 1 : 0, ky1 = (h == 31) ? 1 : 2;
    int kx0 = (w == 0) ? 1 : 0, kx1 = (w == 31) ? 1 : 2;
    const float* hb = ht + ((size_t)n * CD + o) * 9;
    float acc = sc[(size_t)p * CD + o];
    for (int ky = ky0; ky <= ky1; ky++)
        for (int kx = kx0; kx <= kx1; kx++)
            acc += hb[ky * 3 + kx];
    base[(size_t)idx * CD + o] = acc;
}

/* ---------------- q = relu(emb @ qconv_w^T + qconv_b), all steps --------- */
__global__ void qa_k(const float* __restrict__ emb, const float* __restrict__ qw,
                     const float* __restrict__ qb, float* __restrict__ qa)
{
    int s = blockIdx.x, n = blockIdx.y, tid = threadIdx.x;
    __shared__ float e[304];
    for (int i = tid; i < 300; i += CD) e[i] = emb[((size_t)n * SEQL + s) * 300 + i];
    __syncthreads();
    float acc = qb[tid];
    const float* wr = qw + (size_t)tid * 300;
    for (int i = 0; i < 300; i++) acc += e[i] * wr[i];
    qa[((size_t)s * NB + n) * CD + tid] = fmaxf(acc, 0.f);
}

/* ---------------- qh = q @ Wq^T + bq ------------------------------------- */
__global__ void qh_k(const float* __restrict__ qa, const float* __restrict__ ipw,
                     const float* __restrict__ ipb, float* __restrict__ qh)
{
    int s = blockIdx.x, n = blockIdx.y, tid = threadIdx.x;
    __shared__ float q[CD];
    q[tid] = qa[((size_t)s * NB + n) * CD + tid];
    __syncthreads();
    float acc = ipb[tid];
    const float* wr = ipw + (size_t)tid * CD;
    #pragma unroll 4
    for (int i = 0; i < CD; i++) acc += q[i] * wr[i];
    qh[((size_t)s * NB + n) * CD + tid] = acc;
}

/* =================== tf32 tensor-core GEMM, 128x128 tile =================
   4 warps of 64x64 (2M x 2N), BK=32, 3-stage cp.async, fp32 accum.
   Per warp per k-step: 32 LDS : 32 HMMA (was 24:16) -> LDS no longer binds. */
#define AS_STRIDE 36
#define BS_STRIDE 136            /* == 8 mod 32: conflict-free frag loads */
#define ASTG (128*AS_STRIDE)
#define STG_ELEMS (ASTG + 32*BS_STRIDE)   /* 8960 floats per stage */
#define GEMM_SMEM (3*STG_ELEMS*4)         /* 107520 bytes, 3 stages */

#define MMA_TF32(d, a, b) \
    asm volatile("mma.sync.aligned.m16n8k8.row.col.f32.tf32.tf32.f32 " \
                 "{%0,%1,%2,%3}, {%4,%5,%6,%7}, {%8,%9}, {%0,%1,%2,%3};" \
                 : "+f"(d[0]), "+f"(d[1]), "+f"(d[2]), "+f"(d[3]) \
                 : "r"(a[0]), "r"(a[1]), "r"(a[2]), "r"(a[3]), \
                   "r"(b[0]), "r"(b[1]))

template<bool CONV>
__device__ __forceinline__ void load_stage(float* stg, const float* A, const float* B,
                                           int m0, int n0, int k0, int K, int Nout, int tid)
{
    /* A tile 128x32 = 1024 x 16B chunks, 8 per thread (128 thr) */
    #pragma unroll
    for (int pass = 0; pass < 8; pass++) {
        int idx = pass * 128 + tid;
        int row = idx >> 3;
        int k4  = (idx & 7) << 2;
        const float* src;
        int sz = 16;
        if (!CONV) {
            src = A + (size_t)(m0 + row) * K + k0 + k4;
        } else {
            int k = k0 + k4;
            int tap = k >> 8;
            int c = k & 255;
            int dy = tap / 3 - 1, dx = tap % 3 - 1;
            int r = m0 + row;
            int p = r & 1023;
            int h = (p >> 5) + dy, w = (p & 31) + dx;
            if ((unsigned)h < 32u && (unsigned)w < 32u) {
                src = A + (size_t)((r & ~1023) | (h << 5) | w) * 256 + c;
            } else { src = A; sz = 0; }    /* zero-fill */
        }
        cp16((uint32_t)__cvta_generic_to_shared(stg + row * AS_STRIDE + k4), src, sz);
    }
    /* B tile 32x128 = 1024 x 16B chunks, 8 per thread */
    float* bs = stg + ASTG;
    #pragma unroll
    for (int pass = 0; pass < 8; pass++) {
        int idx = pass * 128 + tid;
        int kk = idx >> 5;
        int nn = (idx & 31) << 2;
        cp16((uint32_t)__cvta_generic_to_shared(bs + kk * BS_STRIDE + nn),
             B + (size_t)(k0 + kk) * Nout + n0 + nn, 16);
    }
    CP_COMMIT();
}

template<bool CONV>
__global__ void __launch_bounds__(128, 2)
gemm_k(const float* __restrict__ A, const float* __restrict__ B,
       const float* __restrict__ bias, const float* __restrict__ extra,
       float* __restrict__ C, int M, int Nout, int K, int doRelu)
{
    extern __shared__ float sm[];
    int tid  = threadIdx.x;
    int m0   = blockIdx.y * 128;
    int n0   = blockIdx.x * 128;
    int warp = tid >> 5;
    int lane = tid & 31;
    int wM = warp & 1;              /* M offset 64*wM */
    int wN = warp >> 1;             /* N offset 64*wN */
    int gid = lane >> 2;
    int tig = lane & 3;

    float acc[4][8][4];
    #pragma unroll
    for (int i = 0; i < 4; i++)
        #pragma unroll
        for (int j = 0; j < 8; j++)
            #pragma unroll
            for (int r = 0; r < 4; r++) acc[i][j][r] = 0.f;

    int nk = K >> 5;                /* >= 8 always */
    load_stage<CONV>(sm,             A, B, m0, n0,  0, K, Nout, tid);
    load_stage<CONV>(sm + STG_ELEMS, A, B, m0, n0, 32, K, Nout, tid);

    for (int ki = 0; ki < nk; ki++) {
        if (ki + 2 < nk)
            load_stage<CONV>(sm + ((ki + 2) % 3) * STG_ELEMS, A, B,
                             m0, n0, (ki + 2) << 5, K, Nout, tid);
        else
            CP_COMMIT();            /* empty group keeps count aligned */
        CP_WAIT(2);
        __syncthreads();

        float* As = sm + (ki % 3) * STG_ELEMS;
        float* Bs = As + ASTG;
        #pragma unroll
        for (int ks = 0; ks < 4; ks++) {
            int kb = ks << 3;
            uint32_t a[4][4], b[8][2];
            #pragma unroll
            for (int mf = 0; mf < 4; mf++) {
                int row = wM * 64 + mf * 16 + gid;
                const float* ap = As + row * AS_STRIDE + kb;
                a[mf][0] = __float_as_uint(ap[tig]);
                a[mf][1] = __float_as_uint(ap[8 * AS_STRIDE + tig]);
                a[mf][2] = __float_as_uint(ap[tig + 4]);
                a[mf][3] = __float_as_uint(ap[8 * AS_STRIDE + tig + 4]);
            }
            #pragma unroll
            for (int nf = 0; nf < 8; nf++) {
                int col = wN * 64 + nf * 8 + gid;
                b[nf][0] = __float_as_uint(Bs[(kb + tig) * BS_STRIDE + col]);
                b[nf][1] = __float_as_uint(Bs[(kb + tig + 4) * BS_STRIDE + col]);
            }
            #pragma unroll
            for (int mf = 0; mf < 4; mf++)
                #pragma unroll
                for (int nf = 0; nf < 8; nf++)
                    MMA_TF32(acc[mf][nf], a[mf], b[nf]);
        }
        __syncthreads();
    }

    /* epilogue */
    #pragma unroll
    for (int mf = 0; mf < 4; mf++) {
        int row = m0 + wM * 64 + mf * 16 + gid;
        #pragma unroll
        for (int nf = 0; nf < 8; nf++) {
            int col = n0 + wN * 64 + nf * 8 + 2 * tig;
            float2 v0 = make_float2(acc[mf][nf][0], acc[mf][nf][1]);
            float2 v1 = make_float2(acc[mf][nf][2], acc[mf][nf][3]);
            if (bias) {
                float2 bb = *reinterpret_cast<const float2*>(bias + col);
                v0.x += bb.x; v0.y += bb.y; v1.x += bb.x; v1.y += bb.y;
            }
            if (extra) {
                float2 e0 = *reinterpret_cast<const float2*>(extra + (size_t)row * Nout + col);
                float2 e1 = *reinterpret_cast<const float2*>(extra + (size_t)(row + 8) * Nout + col);
                v0.x += e0.x; v0.y += e0.y; v1.x += e1.x; v1.y += e1.y;
            }
            if (doRelu) {
                v0.x = fmaxf(v0.x, 0.f); v0.y = fmaxf(v0.y, 0.f);
                v1.x = fmaxf(v1.x, 0.f); v1.y = fmaxf(v1.y, 0.f);
            }
            *reinterpret_cast<float2*>(C + (size_t)row * Nout + col) = v0;
            *reinterpret_cast<float2*>(C + (size_t)(row + 8) * Nout + col) = v1;
        }
    }
}

/* ---------------- layernorm, warp-per-row (8 rows / block) --------------- */
__global__ void ln_k(const float* __restrict__ X, const float* __restrict__ g,
                     const float* __restrict__ b, float* __restrict__ Y,
                     const int* __restrict__ words, int step)
{
    if (words && words[step] == 0) return;     /* inactive: keep old state */
    int row  = blockIdx.x * 8 + (threadIdx.x >> 5);
    int lane = threadIdx.x & 31;
    const float* xr = X + (size_t)row * CD;
    float4 u = *reinterpret_cast<const float4*>(xr + lane * 4);
    float4 w = *reinterpret_cast<const float4*>(xr + 128 + lane * 4);
    float s  = u.x + u.y + u.z + u.w + w.x + w.y + w.z + w.w;
    float ss = u.x*u.x + u.y*u.y + u.z*u.z + u.w*u.w
             + w.x*w.x + w.y*w.y + w.z*w.z + w.w*w.w;
    #pragma unroll
    for (int off = 16; off; off >>= 1) {
        s  += __shfl_xor_sync(0xffffffffu, s, off);
        ss += __shfl_xor_sync(0xffffffffu, ss, off);
    }
    float mean = s * (1.f / 256.f);
    float var  = ss * (1.f / 256.f) - mean * mean;
    float inv  = rsqrtf(var + 1e-5f);
    float4 g0 = *reinterpret_cast<const float4*>(g + lane * 4);
    float4 g1 = *reinterpret_cast<const float4*>(g + 128 + lane * 4);
    float4 b0 = *reinterpret_cast<const float4*>(b + lane * 4);
    float4 b1 = *reinterpret_cast<const float4*>(b + 128 + lane * 4);
    float4 y0, y1;
    y0.x = (u.x - mean) * inv * g0.x + b0.x;
    y0.y = (u.y - mean) * inv * g0.y + b0.y;
    y0.z = (u.z - mean) * inv * g0.z + b0.z;
    y0.w = (u.w - mean) * inv * g0.w + b0.w;
    y1.x = (w.x - mean) * inv * g1.x + b1.x;
    y1.y = (w.y - mean) * inv * g1.y + b1.y;
    y1.z = (w.z - mean) * inv * g1.z + b1.z;
    y1.w = (w.w - mean) * inv * g1.w + b1.w;
    float* yr = Y + (size_t)row * CD;
    *reinterpret_cast<float4*>(yr + lane * 4) = y0;
    *reinterpret_cast<float4*>(yr + 128 + lane * 4) = y1;
}

/* ---------------- attention: per (p, head), 16x16 over batch ------------- */
__global__ void attn_k(const float* __restrict__ kv, const float* __restrict__ qh,
                       float* __restrict__ obuf, int step)
{
    int p = blockIdx.x, hd = blockIdx.y;
    int tid = threadIdx.x;
    __shared__ float qs[16][128], ks[16][128], vs[16][128], at[16][17];
    const float* qbase = qh + (size_t)step * NB * CD + hd * 128;
    for (int i = tid; i < 16 * 128; i += 256) {
        int l = i >> 7, d = i & 127;
        qs[l][d] = qbase[(size_t)l * CD + d];
        ks[l][d] = kv[(((size_t)l << 10) + p) * 512 + hd * 128 + d];
        vs[l][d] = kv[(((size_t)l << 10) + p) * 512 + 256 + hd * 128 + d];
    }
    __syncthreads();
    {
        int l = tid >> 4, m = tid & 15;
        float s = 0.f;
        #pragma unroll 8
        for (int d = 0; d < 128; d++) s += qs[l][d] * ks[m][d];
        s *= 0.08838834764831845f;
        float mx = s;
        #pragma unroll
        for (int off = 8; off; off >>= 1) mx = fmaxf(mx, __shfl_xor_sync(0xffffffffu, mx, off));
        float e = expf(s - mx);
        float sum = e;
        #pragma unroll
        for (int off = 8; off; off >>= 1) sum += __shfl_xor_sync(0xffffffffu, sum, off);
        at[l][m] = e / sum;
    }
    __syncthreads();
    {
        int l = tid >> 4;
        int d0 = (tid & 15) * 8;
        float acc[8];
        #pragma unroll
        for (int j = 0; j < 8; j++) acc[j] = 0.f;
        #pragma unroll
        for (int m = 0; m < 16; m++) {
            float a = at[l][m];
            #pragma unroll
            for (int j = 0; j < 8; j++) acc[j] += a * vs[m][d0 + j];
        }
        float* o = obuf + (((size_t)l << 10) + p) * CD + hd * 128 + d0;
        #pragma unroll
        for (int j = 0; j < 8; j++) o[j] = acc[j];
    }
}

/* ======================================================================== */
extern "C" void kernel_launch(void* const* d_in, const int* in_sizes, int n_in,
                              void* d_out, int out_size)
{
    const float* hn      = (const float*)d_in[1];
    const float* feature = (const float*)d_in[2];
    const float* emb     = (const float*)d_in[3];
    const int*   words   = (const int*)  d_in[4];
    const float* qw      = (const float*)d_in[5];
    const float* qb      = (const float*)d_in[6];
    const float* mw      = (const float*)d_in[7];
    const float* mg      = (const float*)d_in[8];
    const float* mb      = (const float*)d_in[9];
    const float* ipw     = (const float*)d_in[10];
    const float* ipb     = (const float*)d_in[11];
    const float* opw     = (const float*)d_in[12];
    const float* opb     = (const float*)d_in[13];
    const float* ng      = (const float*)d_in[14];
    const float* nbv     = (const float*)d_in[15];
    const float* w1      = (const float*)d_in[16];
    const float* b1      = (const float*)d_in[17];
    const float* w2      = (const float*)d_in[18];
    const float* b2      = (const float*)d_in[19];
    const float* nfg     = (const float*)d_in[20];
    const float* nfb     = (const float*)d_in[21];

    float *featT, *base, *t, *fea, *s1, *s2, *kvb;
    float *wConvT, *wkvT, *woT, *w1T, *w2T, *hnTap, *sconv, *qhall, *qall;
    cudaGetSymbolAddress((void**)&featT, g_featT);
    cudaGetSymbolAddress((void**)&base,  g_base);
    cudaGetSymbolAddress((void**)&t,     g_t);
    cudaGetSymbolAddress((void**)&fea,   g_fea);
    cudaGetSymbolAddress((void**)&s1,    g_s1);
    cudaGetSymbolAddress((void**)&s2,    g_s2);
    cudaGetSymbolAddress((void**)&kvb,   g_kv);
    cudaGetSymbolAddress((void**)&wConvT,g_wConvT);
    cudaGetSymbolAddress((void**)&wkvT,  g_wkvT);
    cudaGetSymbolAddress((void**)&woT,   g_woT);
    cudaGetSymbolAddress((void**)&w1T,   g_w1T);
    cudaGetSymbolAddress((void**)&w2T,   g_w2T);
    cudaGetSymbolAddress((void**)&hnTap, g_hnTap);
    cudaGetSymbolAddress((void**)&sconv, g_sconv);
    cudaGetSymbolAddress((void**)&qhall, g_qhall);
    cudaGetSymbolAddress((void**)&qall,  g_qall);

    cudaFuncSetAttribute(gemm_k<true>,  cudaFuncAttributeMaxDynamicSharedMemorySize, GEMM_SMEM);
    cudaFuncSetAttribute(gemm_k<false>, cudaFuncAttributeMaxDynamicSharedMemorySize, GEMM_SMEM);

    /* ---- precompute ---- */
    wtr_k<<<dim3(8, 32, NB), 256>>>(feature, featT, 256, 1024,
                                    (long)256 * 1024, (long)1024 * 256, 0);
    wconv_k<<<KCONV, 256>>>(mw, wConvT);
    wtr_k<<<dim3(16, 8, 1), 256>>>(ipw + 256 * 256, wkvT, 512, 256, 0, 0, 1);
    wtr_k<<<dim3(8, 8, 1), 256>>>(opw, woT, 256, 256, 0, 0, 1);
    wtr_k<<<dim3(8, 8, 1), 256>>>(w1, w1T, 256, 256, 0, 0, 1);
    wtr_k<<<dim3(8, 8, 1), 256>>>(w2, w2T, 256, 256, 0, 0, 1);
    hntap_k<<<NB, 256>>>(hn, mw, hnTap);
    sconv_k<<<PTOT, 256>>>(mw, sconv);
    base_k<<<MROWS, 256>>>(sconv, hnTap, base);
    qa_k<<<dim3(SEQL, NB), 256>>>(emb, qw, qb, qall);
    qh_k<<<dim3(SEQL, NB), 256>>>(qall, ipw, ipb, qhall);

    /* ---- 20 recurrent steps ---- */
    for (int s = 0; s < SEQL; s++) {
        gemm_k<true><<<dim3(2, 128), 128, GEMM_SMEM>>>(featT, wConvT, nullptr, base,
                                                       s1, MROWS, 256, KCONV, 1);
        ln_k<<<2048, 256>>>(s1, mg, mb, t, nullptr, 0);
        gemm_k<false><<<dim3(4, 128), 128, GEMM_SMEM>>>(t, wkvT, ipb + 256, nullptr,
                                                        kvb, MROWS, 512, 256, 0);
        attn_k<<<dim3(PTOT, 2), 256>>>(kvb, qhall, s2, s);
        gemm_k<false><<<dim3(2, 128), 128, GEMM_SMEM>>>(s2, woT, opb, t,
                                                        s1, MROWS, 256, 256, 0);
        ln_k<<<2048, 256>>>(s1, ng, nbv, fea, nullptr, 0);
        gemm_k<false><<<dim3(2, 128), 128, GEMM_SMEM>>>(fea, w1T, b1, nullptr,
                                                        s2, MROWS, 256, 256, 1);
        gemm_k<false><<<dim3(2, 128), 128, GEMM_SMEM>>>(s2, w2T, b2, fea,
                                                        s1, MROWS, 256, 256, 0);
        ln_k<<<2048, 256>>>(s1, nfg, nfb, featT, words, s);
    }

    wtr_k<<<dim3(32, 8, NB), 256>>>(featT, (float*)d_out, 1024, 256,
                                    (long)1024 * 256, (long)256 * 1024, 0);
    (void)in_sizes; (void)n_in; (void)out_size;
}

// round 15
// speedup vs baseline: 1.0545x; 1.0545x over previous
#include <cuda_runtime.h>
#include <math.h>
#include <stdint.h>

#define NB    16
#define PTOT  1024
#define CD    256
#define HND   512
#define SEQL  20
#define MROWS (NB*PTOT)        /* 16384 */
#define KCONV 2304             /* 9 taps * 256 ch */

/* ---------------- scratch (device globals; no allocation allowed) -------- */
__device__ float g_featT [MROWS*CD];
__device__ float g_base  [MROWS*CD];
__device__ float g_t     [MROWS*CD];
__device__ float g_fea   [MROWS*CD];
__device__ float g_s2    [MROWS*CD];
__device__ float g_kv    [MROWS*2*CD];
__device__ float g_wConvT[KCONV*CD];
__device__ float g_wkvT  [CD*2*CD];
__device__ float g_woT   [CD*CD];
__device__ float g_w1T   [CD*CD];
__device__ float g_w2T   [CD*CD];
__device__ float g_hnTap [NB*CD*9];
__device__ float g_sconv [PTOT*CD];
__device__ float g_qhall [SEQL*NB*CD];

/* ---------------- tf32 round helper (precompute only) -------------------- */
__device__ __forceinline__ float ftf32(float x)
{
    uint32_t u;
    asm("cvt.rna.tf32.f32 %0, %1;" : "=r"(u) : "f"(x));
    return __uint_as_float(u);
}

/* ---------------- cp.async helpers --------------------------------------- */
__device__ __forceinline__ void cp16(uint32_t d, const void* s, int sz)
{
    asm volatile("cp.async.cg.shared.global [%0], [%1], 16, %2;"
                 :: "r"(d), "l"(s), "r"(sz));
}
#define CP_COMMIT() asm volatile("cp.async.commit_group;")
#define CP_WAIT(n)  asm volatile("cp.async.wait_group %0;" :: "n"(n))

/* ---------------- batched precompute: wconv + 5 transposes --------------- */
/* flat grid:
   [0,2304)        : conv weight relayout [o][c][tap] -> [tap*256+c][o]
   [2304,2432)     : wkvT   (512x256 transpose, 128 tiles)
   [2432,2496)     : woT    (64 tiles)
   [2496,2560)     : w1T    (64)
   [2560,2624)     : w2T    (64)
   [2624,6720)     : featT  (16 batches x 256 tiles)                       */
__global__ void prew_k(const float* __restrict__ mw, const float* __restrict__ ipw,
                       const float* __restrict__ opw, const float* __restrict__ w1,
                       const float* __restrict__ w2, const float* __restrict__ feature,
                       float* __restrict__ wConvT, float* __restrict__ wkvT,
                       float* __restrict__ woT, float* __restrict__ w1T,
                       float* __restrict__ w2T, float* __restrict__ featT)
{
    int bid = blockIdx.x;
    if (bid < 2304) {
        int tap = bid >> 8, c = bid & 255, o = threadIdx.x;
        wConvT[(size_t)bid * CD + o] = ftf32(mw[((size_t)o * 776 + c) * 9 + tap]);
        return;
    }
    bid -= 2304;
    const float* src; float* dst; int O, Cc, tx, ty, rnd = 1;
    if (bid < 128)      { src = ipw + 256 * 256; dst = wkvT; O = 512; Cc = 256;
                          tx = bid & 15; ty = bid >> 4; }
    else if (bid < 192) { int i = bid - 128; src = opw; dst = woT; O = 256; Cc = 256;
                          tx = i & 7; ty = i >> 3; }
    else if (bid < 256) { int i = bid - 192; src = w1; dst = w1T; O = 256; Cc = 256;
                          tx = i & 7; ty = i >> 3; }
    else if (bid < 320) { int i = bid - 256; src = w2; dst = w2T; O = 256; Cc = 256;
                          tx = i & 7; ty = i >> 3; }
    else                { int i = bid - 320; int n = i >> 8; int t = i & 255;
                          src = feature + (size_t)n * CD * PTOT;
                          dst = featT + (size_t)n * PTOT * CD;
                          O = 256; Cc = 1024; tx = t & 7; ty = t >> 3; rnd = 0; }
    __shared__ float tile[32][33];
    int o0 = tx * 32, c0 = ty * 32;
    int lx = threadIdx.x & 31, ly = threadIdx.x >> 5;
    #pragma unroll
    for (int i = ly; i < 32; i += 8)
        tile[i][lx] = src[(size_t)(o0 + i) * Cc + c0 + lx];
    __syncthreads();
    #pragma unroll
    for (int i = ly; i < 32; i += 8) {
        float v = tile[lx][i];
        dst[(size_t)(c0 + i) * O + o0 + lx] = rnd ? ftf32(v) : v;
    }
}

/* ---------------- generic transpose (final output only) ------------------ */
__global__ void wtr_k(const float* __restrict__ src, float* __restrict__ dst,
                      int O, int Cc, long sStride, long dStride)
{
    src += (size_t)blockIdx.z * sStride;
    dst += (size_t)blockIdx.z * dStride;
    __shared__ float tile[32][33];
    int o0 = blockIdx.x * 32, c0 = blockIdx.y * 32;
    int lx = threadIdx.x & 31, ly = threadIdx.x >> 5;
    #pragma unroll
    for (int i = ly; i < 32; i += 8)
        tile[i][lx] = src[(size_t)(o0 + i) * Cc + c0 + lx];
    __syncthreads();
    #pragma unroll
    for (int i = ly; i < 32; i += 8)
        dst[(size_t)(c0 + i) * O + o0 + lx] = tile[lx][i];
}

/* ---------------- hn tap sums -------------------------------------------- */
__global__ void hntap_k(const float* __restrict__ hn, const float* __restrict__ mw,
                        float* __restrict__ out)
{
    int n = blockIdx.x, o = threadIdx.x;
    __shared__ float h[HND];
    for (int i = o; i < HND; i += CD) h[i] = hn[(size_t)n * HND + i];
    __syncthreads();
    float acc[9];
    #pragma unroll
    for (int t = 0; t < 9; t++) acc[t] = 0.f;
    const float* wb = mw + ((size_t)o * 776 + 264) * 9;
    for (int c = 0; c < HND; c++) {
        float hv = h[c];
        #pragma unroll
        for (int t = 0; t < 9; t++) acc[t] += hv * wb[c * 9 + t];
    }
    #pragma unroll
    for (int t = 0; t < 9; t++) out[((size_t)n * CD + o) * 9 + t] = acc[t];
}

/* ---------------- spatial conv (invariant) ------------------------------- */
__global__ void sconv_k(const float* __restrict__ mw, float* __restrict__ out)
{
    int p = blockIdx.x, o = threadIdx.x;
    int h = p >> 5, w = p & 31;
    float acc = 0.f;
    const float* wb = mw + ((size_t)o * 776 + 256) * 9;
    for (int ky = 0; ky < 3; ky++) {
        int hh = h + ky - 1; if ((unsigned)hh >= 32u) continue;
        for (int kx = 0; kx < 3; kx++) {
            int ww = w + kx - 1; if ((unsigned)ww >= 32u) continue;
            float xmin = ww * (1.f/16.f) - 1.f, ymin = hh * (1.f/16.f) - 1.f;
            float xmax = (ww + 1) * (1.f/16.f) - 1.f, ymax = (hh + 1) * (1.f/16.f) - 1.f;
            float f[8] = {xmin, ymin, xmax, ymax,
                          0.5f*(xmin+xmax), 0.5f*(ymin+ymax), 1.f/32.f, 1.f/32.f};
            int t = ky * 3 + kx;
            #pragma unroll
            for (int c = 0; c < 8; c++) acc += f[c] * wb[c * 9 + t];
        }
    }
    out[(size_t)p * CD + o] = acc;
}

/* ---------------- base[n][p][o] = sconv + border-case hn taps ------------ */
__global__ void base_k(const float* __restrict__ sc, const float* __restrict__ ht,
                       float* __restrict__ base)
{
    int idx = blockIdx.x;
    int n = idx >> 10, p = idx & 1023;
    int o = threadIdx.x;
    int h = p >> 5, w = p & 31;
    int ky0 = (h == 0) ? 1 : 0, ky1 = (h == 31) ? 1 : 2;
    int kx0 = (w == 0) ? 1 : 0, kx1 = (w == 31) ? 1 : 2;
    const float* hb = ht + ((size_t)n * CD + o) * 9;
    float acc = sc[(size_t)p * CD + o];
    for (int ky = ky0; ky <= ky1; ky++)
        for (int kx = kx0; kx <= kx1; kx++)
            acc += hb[ky * 3 + kx];
    base[(size_t)idx * CD + o] = acc;
}

/* ---------------- fused qa+qh: qh = relu(emb@qw^T+qb) @ Wq^T + bq -------- */
__global__ void qaqh_k(const float* __restrict__ emb, const float* __restrict__ qw,
                       const float* __restrict__ qb, const float* __restrict__ ipw,
                       const float* __restrict__ ipb, float* __restrict__ qh)
{
    int s = blockIdx.x, n = blockIdx.y, tid = threadIdx.x;
    __shared__ float e[304];
    __shared__ float q[CD];
    for (int i = tid; i < 300; i += CD) e[i] = emb[((size_t)n * SEQL + s) * 300 + i];
    __syncthreads();
    float acc = qb[tid];
    const float* wr = qw + (size_t)tid * 300;
    for (int i = 0; i < 300; i++) acc += e[i] * wr[i];
    q[tid] = fmaxf(acc, 0.f);
    __syncthreads();
    float a2 = ipb[tid];
    const float* w2r = ipw + (size_t)tid * CD;
    #pragma unroll 4
    for (int i = 0; i < CD; i++) a2 += q[i] * w2r[i];
    qh[((size_t)s * NB + n) * CD + tid] = a2;
}

/* ======== shared MMA macro ======== */
#define MMA_TF32(d, a, b) \
    asm volatile("mma.sync.aligned.m16n8k8.row.col.f32.tf32.tf32.f32 " \
                 "{%0,%1,%2,%3}, {%4,%5,%6,%7}, {%8,%9}, {%0,%1,%2,%3};" \
                 : "+f"(d[0]), "+f"(d[1]), "+f"(d[2]), "+f"(d[3]) \
                 : "r"(a[0]), "r"(a[1]), "r"(a[2]), "r"(a[3]), \
                   "r"(b[0]), "r"(b[1]))

/* =================== kv GEMM: 128x128 tile (R10-best config) ============= */
#define AS_STRIDE 36
#define BS_STRIDE 136
#define ASTG (128*AS_STRIDE)
#define STG_ELEMS (ASTG + 32*BS_STRIDE)
#define GEMM_SMEM (2*STG_ELEMS*4)

__device__ __forceinline__ void load_stage(float* stg, const float* A, const float* B,
                                           int m0, int n0, int k0, int K, int Nout, int tid)
{
    #pragma unroll
    for (int pass = 0; pass < 4; pass++) {
        int idx = pass * 256 + tid;
        int row = idx >> 3;
        int k4  = (idx & 7) << 2;
        cp16((uint32_t)__cvta_generic_to_shared(stg + row * AS_STRIDE + k4),
             A + (size_t)(m0 + row) * K + k0 + k4, 16);
    }
    float* bs = stg + ASTG;
    #pragma unroll
    for (int pass = 0; pass < 4; pass++) {
        int idx = pass * 256 + tid;
        int kk = idx >> 5;
        int nn = (idx & 31) << 2;
        cp16((uint32_t)__cvta_generic_to_shared(bs + kk * BS_STRIDE + nn),
             B + (size_t)(k0 + kk) * Nout + n0 + nn, 16);
    }
    CP_COMMIT();
}

__global__ void __launch_bounds__(256, 2)
gemm_k(const float* __restrict__ A, const float* __restrict__ B,
       const float* __restrict__ bias, float* __restrict__ C,
       int Nout, int K)
{
    extern __shared__ float sm[];
    int tid  = threadIdx.x;
    int m0   = blockIdx.y * 128;
    int n0   = blockIdx.x * 128;
    int warp = tid >> 5;
    int lane = tid & 31;
    int wM = warp & 3;
    int wN = warp >> 2;
    int gid = lane >> 2;
    int tig = lane & 3;

    float acc[2][8][4];
    #pragma unroll
    for (int i = 0; i < 2; i++)
        #pragma unroll
        for (int j = 0; j < 8; j++)
            #pragma unroll
            for (int r = 0; r < 4; r++) acc[i][j][r] = 0.f;

    int nk = K >> 5;
    load_stage(sm, A, B, m0, n0, 0, K, Nout, tid);

    for (int ki = 0; ki < nk; ki++) {
        float* As = sm + (ki & 1) * STG_ELEMS;
        float* Bs = As + ASTG;
        if (ki + 1 < nk) {
            load_stage(sm + ((ki + 1) & 1) * STG_ELEMS, A, B,
                       m0, n0, (ki + 1) << 5, K, Nout, tid);
            CP_WAIT(1);
        } else {
            CP_WAIT(0);
        }
        __syncthreads();

        #pragma unroll
        for (int ks = 0; ks < 4; ks++) {
            int kb = ks << 3;
            uint32_t a[2][4], b[8][2];
            #pragma unroll
            for (int mf = 0; mf < 2; mf++) {
                int row = wM * 32 + mf * 16 + gid;
                const float* ap = As + row * AS_STRIDE + kb;
                a[mf][0] = __float_as_uint(ap[tig]);
                a[mf][1] = __float_as_uint(ap[8 * AS_STRIDE + tig]);
                a[mf][2] = __float_as_uint(ap[tig + 4]);
                a[mf][3] = __float_as_uint(ap[8 * AS_STRIDE + tig + 4]);
            }
            #pragma unroll
            for (int nf = 0; nf < 8; nf++) {
                int col = wN * 64 + nf * 8 + gid;
                b[nf][0] = __float_as_uint(Bs[(kb + tig) * BS_STRIDE + col]);
                b[nf][1] = __float_as_uint(Bs[(kb + tig + 4) * BS_STRIDE + col]);
            }
            #pragma unroll
            for (int mf = 0; mf < 2; mf++)
                #pragma unroll
                for (int nf = 0; nf < 8; nf++)
                    MMA_TF32(acc[mf][nf], a[mf], b[nf]);
        }
        __syncthreads();
    }

    #pragma unroll
    for (int mf = 0; mf < 2; mf++) {
        int row = m0 + wM * 32 + mf * 16 + gid;
        #pragma unroll
        for (int nf = 0; nf < 8; nf++) {
            int col = n0 + wN * 64 + nf * 8 + 2 * tig;
            float2 bb = *reinterpret_cast<const float2*>(bias + col);
            float2 v0 = make_float2(acc[mf][nf][0] + bb.x, acc[mf][nf][1] + bb.y);
            float2 v1 = make_float2(acc[mf][nf][2] + bb.x, acc[mf][nf][3] + bb.y);
            *reinterpret_cast<float2*>(C + (size_t)row * Nout + col) = v0;
            *reinterpret_cast<float2*>(C + (size_t)(row + 8) * Nout + col) = v1;
        }
    }
}

/* =================== fused GEMM(+bias,+extra,+relu)+LayerNorm ============
   CTA tile 128 x 256 (full LN row).  256 thr = 8 warps (2M x 4N),
   warp tile 64x64 = 4x8 m16n8k8, BK=32, 2-stage cp.async.
   Epilogue: bias+extra+relu, then optional LN (intra-warp shfl over tig,
   cross-warp via SMEM), optional conditional commit (words).              */
#define FBS_STRIDE 264          /* == 8 mod 32 */
#define FASTG (128*AS_STRIDE)   /* 4608 */
#define FSTG (FASTG + 32*FBS_STRIDE)   /* 13056 floats */
#define FGEMM_SMEM (2*FSTG*4)          /* 104448 bytes */

template<bool CONV>
__device__ __forceinline__ void fload_stage(float* stg, const float* A, const float* B,
                                            int m0, int k0, int K, int tid)
{
    #pragma unroll
    for (int pass = 0; pass < 4; pass++) {
        int idx = pass * 256 + tid;
        int row = idx >> 3;
        int k4  = (idx & 7) << 2;
        const float* src;
        int sz = 16;
        if (!CONV) {
            src = A + (size_t)(m0 + row) * K + k0 + k4;
        } else {
            int k = k0 + k4;
            int tap = k >> 8;
            int c = k & 255;
            int dy = tap / 3 - 1, dx = tap % 3 - 1;
            int r = m0 + row;
            int p = r & 1023;
            int h = (p >> 5) + dy, w = (p & 31) + dx;
            if ((unsigned)h < 32u && (unsigned)w < 32u) {
                src = A + (size_t)((r & ~1023) | (h << 5) | w) * 256 + c;
            } else { src = A; sz = 0; }
        }
        cp16((uint32_t)__cvta_generic_to_shared(stg + row * AS_STRIDE + k4), src, sz);
    }
    float* bs = stg + FASTG;
    #pragma unroll
    for (int pass = 0; pass < 8; pass++) {
        int idx = pass * 256 + tid;
        int kk = idx >> 6;
        int nn = (idx & 63) << 2;
        cp16((uint32_t)__cvta_generic_to_shared(bs + kk * FBS_STRIDE + nn),
             B + (size_t)(k0 + kk) * CD + nn, 16);
    }
    CP_COMMIT();
}

template<bool CONV>
__global__ void __launch_bounds__(256, 1)
gemmln_k(const float* __restrict__ A, const float* __restrict__ B,
         const float* __restrict__ bias, const float* __restrict__ extra,
         float* __restrict__ C, int K, int doRelu,
         const float* __restrict__ g, const float* __restrict__ b,
         const int* __restrict__ words, int step)
{
    if (words && words[step] == 0) return;     /* inactive step: skip all */
    extern __shared__ float sm[];
    int tid  = threadIdx.x;
    int m0   = blockIdx.x * 128;
    int warp = tid >> 5;
    int lane = tid & 31;
    int wM = warp & 1;              /* M offset 64*wM */
    int wN = warp >> 1;             /* N offset 64*wN */
    int gid = lane >> 2;
    int tig = lane & 3;

    float acc[4][8][4];
    #pragma unroll
    for (int i = 0; i < 4; i++)
        #pragma unroll
        for (int j = 0; j < 8; j++)
            #pragma unroll
            for (int r = 0; r < 4; r++) acc[i][j][r] = 0.f;

    int nk = K >> 5;
    fload_stage<CONV>(sm, A, B, m0, 0, K, tid);

    for (int ki = 0; ki < nk; ki++) {
        float* As = sm + (ki & 1) * FSTG;
        float* Bs = As + FASTG;
        if (ki + 1 < nk) {
            fload_stage<CONV>(sm + ((ki + 1) & 1) * FSTG, A, B,
                              m0, (ki + 1) << 5, K, tid);
            CP_WAIT(1);
        } else {
            CP_WAIT(0);
        }
        __syncthreads();

        #pragma unroll
        for (int ks = 0; ks < 4; ks++) {
            int kb = ks << 3;
            uint32_t a[4][4], bb[8][2];
            #pragma unroll
            for (int mf = 0; mf < 4; mf++) {
                int row = wM * 64 + mf * 16 + gid;
                const float* ap = As + row * AS_STRIDE + kb;
                a[mf][0] = __float_as_uint(ap[tig]);
                a[mf][1] = __float_as_uint(ap[8 * AS_STRIDE + tig]);
                a[mf][2] = __float_as_uint(ap[tig + 4]);
                a[mf][3] = __float_as_uint(ap[8 * AS_STRIDE + tig + 4]);
            }
            #pragma unroll
            for (int nf = 0; nf < 8; nf++) {
                int col = wN * 64 + nf * 8 + gid;
                bb[nf][0] = __float_as_uint(Bs[(kb + tig) * FBS_STRIDE + col]);
                bb[nf][1] = __float_as_uint(Bs[(kb + tig + 4) * FBS_STRIDE + col]);
            }
            #pragma unroll
            for (int mf = 0; mf < 4; mf++)
                #pragma unroll
                for (int nf = 0; nf < 8; nf++)
                    MMA_TF32(acc[mf][nf], a[mf], bb[nf]);
        }
        __syncthreads();
    }

    /* ---- epilogue: bias + extra + relu ---- */
    #pragma unroll
    for (int mf = 0; mf < 4; mf++) {
        int row = m0 + wM * 64 + mf * 16 + gid;
        #pragma unroll
        for (int nf = 0; nf < 8; nf++) {
            int col = wN * 64 + nf * 8 + 2 * tig;
            float* v = acc[mf][nf];
            if (bias) {
                float2 bv = *reinterpret_cast<const float2*>(bias + col);
                v[0] += bv.x; v[1] += bv.y; v[2] += bv.x; v[3] += bv.y;
            }
            if (extra) {
                float2 e0 = *reinterpret_cast<const float2*>(extra + (size_t)row * CD + col);
                float2 e1 = *reinterpret_cast<const float2*>(extra + (size_t)(row + 8) * CD + col);
                v[0] += e0.x; v[1] += e0.y; v[2] += e1.x; v[3] += e1.y;
            }
            if (doRelu) {
                v[0] = fmaxf(v[0], 0.f); v[1] = fmaxf(v[1], 0.f);
                v[2] = fmaxf(v[2], 0.f); v[3] = fmaxf(v[3], 0.f);
            }
        }
    }

    if (!g) {   /* no LN (lin1): plain store */
        #pragma unroll
        for (int mf = 0; mf < 4; mf++) {
            int row = m0 + wM * 64 + mf * 16 + gid;
            #pragma unroll
            for (int nf = 0; nf < 8; nf++) {
                int col = wN * 64 + nf * 8 + 2 * tig;
                *reinterpret_cast<float2*>(C + (size_t)row * CD + col) =
                    make_float2(acc[mf][nf][0], acc[mf][nf][1]);
                *reinterpret_cast<float2*>(C + (size_t)(row + 8) * CD + col) =
                    make_float2(acc[mf][nf][2], acc[mf][nf][3]);
            }
        }
        return;
    }

    /* ---- LayerNorm over the full 256-col row ---- */
    float* red_s  = sm;          /* 128 rows x 4 warps */
    float* red_ss = sm + 512;
    #pragma unroll
    for (int mf = 0; mf < 4; mf++) {
        float s0 = 0.f, q0 = 0.f, s1 = 0.f, q1 = 0.f;
        #pragma unroll
        for (int nf = 0; nf < 8; nf++) {
            float* v = acc[mf][nf];
            s0 += v[0] + v[1]; q0 += v[0]*v[0] + v[1]*v[1];
            s1 += v[2] + v[3]; q1 += v[2]*v[2] + v[3]*v[3];
        }
        #pragma unroll
        for (int off = 1; off <= 2; off <<= 1) {
            s0 += __shfl_xor_sync(0xffffffffu, s0, off);
            q0 += __shfl_xor_sync(0xffffffffu, q0, off);
            s1 += __shfl_xor_sync(0xffffffffu, s1, off);
            q1 += __shfl_xor_sync(0xffffffffu, q1, off);
        }
        if (tig == 0) {
            int r = wM * 64 + mf * 16 + gid;
            red_s [r * 4 + wN] = s0;  red_ss[r * 4 + wN] = q0;
            red_s [(r + 8) * 4 + wN] = s1;  red_ss[(r + 8) * 4 + wN] = q1;
        }
    }
    __syncthreads();

    float2 gv[8], bv2[8];
    #pragma unroll
    for (int nf = 0; nf < 8; nf++) {
        int col = wN * 64 + nf * 8 + 2 * tig;
        gv[nf]  = *reinterpret_cast<const float2*>(g + col);
        bv2[nf] = *reinterpret_cast<const float2*>(b + col);
    }
    #pragma unroll
    for (int mf = 0; mf < 4; mf++) {
        int rl = wM * 64 + mf * 16 + gid;
        #pragma unroll
        for (int half = 0; half < 2; half++) {
            int r = rl + half * 8;
            float s = red_s[r*4] + red_s[r*4+1] + red_s[r*4+2] + red_s[r*4+3];
            float q = red_ss[r*4] + red_ss[r*4+1] + red_ss[r*4+2] + red_ss[r*4+3];
            float mean = s * (1.f / 256.f);
            float var  = q * (1.f / 256.f) - mean * mean;
            float inv  = rsqrtf(var + 1e-5f);
            int grow = m0 + r;
            #pragma unroll
            for (int nf = 0; nf < 8; nf++) {
                int col = wN * 64 + nf * 8 + 2 * tig;
                float* v = acc[mf][nf];
                float y0 = (v[half*2]     - mean) * inv * gv[nf].x + bv2[nf].x;
                float y1 = (v[half*2 + 1] - mean) * inv * gv[nf].y + bv2[nf].y;
                *reinterpret_cast<float2*>(C + (size_t)grow * CD + col) =
                    make_float2(y0, y1);
            }
        }
    }
}

/* ---------------- attention: per (p, head), 16x16 over batch ------------- */
__global__ void attn_k(const float* __restrict__ kv, const float* __restrict__ qh,
                       float* __restrict__ obuf, int step)
{
    int p = blockIdx.x, hd = blockIdx.y;
    int tid = threadIdx.x;
    __shared__ float qs[16][128], ks[16][128], vs[16][128], at[16][17];
    const float* qbase = qh + (size_t)step * NB * CD + hd * 128;
    for (int i = tid; i < 16 * 128; i += 256) {
        int l = i >> 7, d = i & 127;
        qs[l][d] = qbase[(size_t)l * CD + d];
        ks[l][d] = kv[(((size_t)l << 10) + p) * 512 + hd * 128 + d];
        vs[l][d] = kv[(((size_t)l << 10) + p) * 512 + 256 + hd * 128 + d];
    }
    __syncthreads();
    {
        int l = tid >> 4, m = tid & 15;
        float s = 0.f;
        #pragma unroll 8
        for (int d = 0; d < 128; d++) s += qs[l][d] * ks[m][d];
        s *= 0.08838834764831845f;
        float mx = s;
        #pragma unroll
        for (int off = 8; off; off >>= 1) mx = fmaxf(mx, __shfl_xor_sync(0xffffffffu, mx, off));
        float e = expf(s - mx);
        float sum = e;
        #pragma unroll
        for (int off = 8; off; off >>= 1) sum += __shfl_xor_sync(0xffffffffu, sum, off);
        at[l][m] = e / sum;
    }
    __syncthreads();
    {
        int l = tid >> 4;
        int d0 = (tid & 15) * 8;
        float acc[8];
        #pragma unroll
        for (int j = 0; j < 8; j++) acc[j] = 0.f;
        #pragma unroll
        for (int m = 0; m < 16; m++) {
            float a = at[l][m];
            #pragma unroll
            for (int j = 0; j < 8; j++) acc[j] += a * vs[m][d0 + j];
        }
        float* o = obuf + (((size_t)l << 10) + p) * CD + hd * 128 + d0;
        #pragma unroll
        for (int j = 0; j < 8; j++) o[j] = acc[j];
    }
}

/* ======================================================================== */
extern "C" void kernel_launch(void* const* d_in, const int* in_sizes, int n_in,
                              void* d_out, int out_size)
{
    const float* hn      = (const float*)d_in[1];
    const float* feature = (const float*)d_in[2];
    const float* emb     = (const float*)d_in[3];
    const int*   words   = (const int*)  d_in[4];
    const float* qw      = (const float*)d_in[5];
    const float* qb      = (const float*)d_in[6];
    const float* mw      = (const float*)d_in[7];
    const float* mg      = (const float*)d_in[8];
    const float* mb      = (const float*)d_in[9];
    const float* ipw     = (const float*)d_in[10];
    const float* ipb     = (const float*)d_in[11];
    const float* opw     = (const float*)d_in[12];
    const float* opb     = (const float*)d_in[13];
    const float* ng      = (const float*)d_in[14];
    const float* nbv     = (const float*)d_in[15];
    const float* w1      = (const float*)d_in[16];
    const float* b1      = (const float*)d_in[17];
    const float* w2      = (const float*)d_in[18];
    const float* b2      = (const float*)d_in[19];
    const float* nfg     = (const float*)d_in[20];
    const float* nfb     = (const float*)d_in[21];

    float *featT, *base, *t, *fea, *s2, *kvb;
    float *wConvT, *wkvT, *woT, *w1T, *w2T, *hnTap, *sconv, *qhall;
    cudaGetSymbolAddress((void**)&featT, g_featT);
    cudaGetSymbolAddress((void**)&base,  g_base);
    cudaGetSymbolAddress((void**)&t,     g_t);
    cudaGetSymbolAddress((void**)&fea,   g_fea);
    cudaGetSymbolAddress((void**)&s2,    g_s2);
    cudaGetSymbolAddress((void**)&kvb,   g_kv);
    cudaGetSymbolAddress((void**)&wConvT,g_wConvT);
    cudaGetSymbolAddress((void**)&wkvT,  g_wkvT);
    cudaGetSymbolAddress((void**)&woT,   g_woT);
    cudaGetSymbolAddress((void**)&w1T,   g_w1T);
    cudaGetSymbolAddress((void**)&w2T,   g_w2T);
    cudaGetSymbolAddress((void**)&hnTap, g_hnTap);
    cudaGetSymbolAddress((void**)&sconv, g_sconv);
    cudaGetSymbolAddress((void**)&qhall, g_qhall);

    cudaFuncSetAttribute(gemm_k, cudaFuncAttributeMaxDynamicSharedMemorySize, GEMM_SMEM);
    cudaFuncSetAttribute(gemmln_k<true>,  cudaFuncAttributeMaxDynamicSharedMemorySize, FGEMM_SMEM);
    cudaFuncSetAttribute(gemmln_k<false>, cudaFuncAttributeMaxDynamicSharedMemorySize, FGEMM_SMEM);

    /* ---- precompute: exactly 5 launches so ncu (-s 5) hits the conv GEMM */
    prew_k<<<6720, 256>>>(mw, ipw, opw, w1, w2, feature,
                          wConvT, wkvT, woT, w1T, w2T, featT);
    hntap_k<<<NB, 256>>>(hn, mw, hnTap);
    sconv_k<<<PTOT, 256>>>(mw, sconv);
    base_k<<<MROWS, 256>>>(sconv, hnTap, base);
    qaqh_k<<<dim3(SEQL, NB), 256>>>(emb, qw, qb, ipw, ipb, qhall);

    /* ---- 20 recurrent steps, 6 launches each ---- */
    for (int s = 0; s < SEQL; s++) {
        /* t = LN(relu(conv(feat) + base)) */
        gemmln_k<true><<<128, 256, FGEMM_SMEM>>>(featT, wConvT, nullptr, base,
                                                 t, KCONV, 1, mg, mb, nullptr, 0);
        /* kv = t @ [Wk;Wv]^T + b */
        gemm_k<<<dim3(4, 128), 256, GEMM_SMEM>>>(t, wkvT, ipb + 256, kvb, 512, 256);
        attn_k<<<dim3(PTOT, 2), 256>>>(kvb, qhall, s2, s);
        /* fea = LN(t + o@Wo^T + bo) */
        gemmln_k<false><<<128, 256, FGEMM_SMEM>>>(s2, woT, opb, t,
                                                  fea, 256, 0, ng, nbv, nullptr, 0);
        /* s2 = relu(fea@W1^T + b1) */
        gemmln_k<false><<<128, 256, FGEMM_SMEM>>>(fea, w1T, b1, nullptr,
                                                  s2, 256, 1, nullptr, nullptr, nullptr, 0);
        /* featT = LN(fea + s2@W2^T + b2)  [conditional commit] */
        gemmln_k<false><<<128, 256, FGEMM_SMEM>>>(s2, w2T, b2, fea,
                                                  featT, 256, 0, nfg, nfb, words, s);
    }

    wtr_k<<<dim3(32, 8, NB), 256>>>(featT, (float*)d_out, 1024, 256,
                                    (long)1024 * 256, (long)256 * 1024);
    (void)in_sizes; (void)n_in; (void)out_size;
}